// round 14
// baseline (speedup 1.0000x reference)
#include <cuda_runtime.h>
#include <math.h>
#include <stdint.h>

// Problem constants
#define U      128
#define NC     10
#define NF     3
#define TT     1000
#define BB     256
#define CSZ    4              // CTAs per cluster
#define GC     8              // batch elements per cluster
#define OWN    32             // units owned per CTA
#define NTHR   512            // group A (0-255) recurrence path, group B (256-511) off-path
#define NCTA   128            // (BB/GC)*CSZ
#define HR     132            // h row stride in floats ([b][u] layout, bank-skewed, 16B-mult)

#define R_ON_   0.05f
#define ALPHA_  0.001f
#define LN_EPS_ 1e-3f

// ---- packed f32x2 helpers (FFMA2: 2x fp32 MAC throughput) ----
__device__ __forceinline__ unsigned long long pack2(float a, float b) {
    unsigned long long r;
    asm("mov.b64 %0, {%1, %2};" : "=l"(r) : "f"(a), "f"(b));
    return r;
}
__device__ __forceinline__ void fma2p(unsigned long long& acc,
                                      unsigned long long a,
                                      unsigned long long b) {
    asm("fma.rn.f32x2 %0, %1, %2, %0;" : "+l"(acc) : "l"(a), "l"(b));
}

// ---- fast transcendental helpers (rel err ~1e-6, budget is 1e-3) ----
__device__ __forceinline__ float fsig(float x) {
    return __fdividef(1.0f, 1.0f + __expf(-x));
}
__device__ __forceinline__ float ftanh(float x) {
    float ax = fabsf(x);
    float e  = __expf(-2.0f * ax);
    float t  = __fdividef(1.0f - e, 1.0f + e);
    return copysignf(t, x);
}

#define CLUSTER_SYNC() do { \
    asm volatile("barrier.cluster.arrive.aligned;" ::: "memory"); \
    asm volatile("barrier.cluster.wait.aligned;"   ::: "memory"); } while (0)

// ---- DSMEM stores (packed) ----
__device__ __forceinline__ void stc_f32(uint32_t la, uint32_t r, float v) {
    uint32_t ra;
    asm volatile("mapa.shared::cluster.u32 %0, %1, %2;" : "=r"(ra) : "r"(la), "r"(r));
    asm volatile("st.shared::cluster.f32 [%0], %1;" :: "r"(ra), "f"(v) : "memory");
}
__device__ __forceinline__ void stc_v2(uint32_t la, uint32_t r, float a, float b) {
    uint32_t ra;
    asm volatile("mapa.shared::cluster.u32 %0, %1, %2;" : "=r"(ra) : "r"(la), "r"(r));
    asm volatile("st.shared::cluster.v2.f32 [%0], {%1, %2};"
                 :: "r"(ra), "f"(a), "f"(b) : "memory");
}
__device__ __forceinline__ void stc_v4(uint32_t la, uint32_t r,
                                       float a, float b, float c, float d) {
    uint32_t ra;
    asm volatile("mapa.shared::cluster.u32 %0, %1, %2;" : "=r"(ra) : "r"(la), "r"(r));
    asm volatile("st.shared::cluster.v4.f32 [%0], {%1, %2, %3, %4};"
                 :: "r"(ra), "f"(a), "f"(b), "f"(c), "f"(d) : "memory");
}

// ---- mbarrier cluster sync ----
__device__ __forceinline__ void mbar_init(uint32_t la, uint32_t cnt) {
    asm volatile("mbarrier.init.shared.b64 [%0], %1;" :: "r"(la), "r"(cnt) : "memory");
}
__device__ __forceinline__ void mbar_arrive_all(uint32_t la) {
    #pragma unroll
    for (uint32_t r = 0; r < CSZ; ++r) {
        uint32_t ra;
        asm volatile("mapa.shared::cluster.u32 %0, %1, %2;" : "=r"(ra) : "r"(la), "r"(r));
        asm volatile("mbarrier.arrive.release.cluster.shared::cluster.b64 _, [%0];"
                     :: "r"(ra) : "memory");
    }
}
#define MBAR_WAIT(mb, ph) do {                                                        \
    uint32_t _go;                                                                     \
    asm volatile("{\n\t.reg .pred p;\n\t"                                             \
        "mbarrier.try_wait.parity.acquire.cluster.shared::cta.b64 p, [%1], %2;\n\t"   \
        "selp.b32 %0, 1, 0, p;\n\t}"                                                  \
        : "=r"(_go) : "r"(mb), "r"((uint32_t)(ph)) : "memory");                       \
    if (!_go) {                                                                       \
        asm volatile("{\n\t.reg .pred P1;\n\t"                                        \
            "WL_%=:\n\t"                                                              \
            "mbarrier.try_wait.parity.acquire.cluster.shared::cta.b64 P1, [%0], %1, 0x989680;\n\t" \
            "@P1 bra.uni WD_%=;\n\t"                                                  \
            "bra.uni WL_%=;\n\t"                                                      \
            "WD_%=:\n\t}"                                                             \
            :: "r"(mb), "r"((uint32_t)(ph)) : "memory");                              \
    }                                                                                 \
} while (0)

// Dynamic SMEM: ~229.9 KB (<= 232448 B limit, 1 CTA/SM)
struct __align__(16) SM {
    float Wh0s[128 * 128];      // own 128 cols (gate-interleaved) of Wh0, plain [k][lc]
    float Wx1g[128 * 128];      // own cols of Wx1 * gamma[k]
    float Wh1s[128 * 128];
    float z0[2 * 8 * 128];      // layer-0 pre-activations [ks][b][lc]
    float z1[2 * 8 * 128];      // layer-1 pre-activations (pre-fold + fold)
    float h0f[GC * HR];         // h0, [b*HR + unit], single-buffered
    float h1f[GC * HR];         // h1, same layout
    float Wx0s[NF * 128];       // own cols of Wx0 [f][lc]
    float b0s[128], b1s[128];   // own cols of biases
    float S1cs[2][128];         // per-slab col sums of Wx1g
    float S2cs[2][128];         // per-slab col sums of Wx1*beta
    float tau0s[OWN], s0s[OWN], itau0s[OWN];
    float tau1s[OWN], s1s[OWN], itau1s[OWN];
    float Wfcs[OWN * NC + 32];  // own rows of Wfc (padded)
    float bfcs[16];
    float2 red2[CSZ * GC];      // LN partials {sum, sumsq} [srcRank*8 + b]
    float lrecv[2][CSZ * 2 * 16];  // logit partials, double-buffered by parity
    float xb[2][GC][4];         // double-buffered inputs (f padded to 4)
    float tmb[2][GC];           // double-buffered times
    unsigned long long mbars[2];   // S1 / S2 cluster mbarriers
};

// One 64-row K-slab: 4 cols (quad) x 2 batches (bpair) per thread.
__device__ __forceinline__ void mv2(const float* __restrict__ Ws,
                                    const float* __restrict__ hb0,
                                    int kbase, int quad,
                                    unsigned long long acc[2][2]) {
    const ulonglong2* w2 = reinterpret_cast<const ulonglong2*>(Ws + kbase * 128) + quad;
    const float* h0p = hb0 + kbase;          // batch 2bp
    const float* h1p = hb0 + HR + kbase;     // batch 2bp+1
    #pragma unroll 8
    for (int k4 = 0; k4 < 16; ++k4) {
        float4 ha = *reinterpret_cast<const float4*>(h0p + 4 * k4);
        float4 hb = *reinterpret_cast<const float4*>(h1p + 4 * k4);
        float hav[4] = {ha.x, ha.y, ha.z, ha.w};
        float hbv[4] = {hb.x, hb.y, hb.z, hb.w};
        #pragma unroll
        for (int j = 0; j < 4; ++j) {
            ulonglong2 w = w2[(4 * k4 + j) * 32];
            unsigned long long hd0 = pack2(hav[j], hav[j]);
            unsigned long long hd1 = pack2(hbv[j], hbv[j]);
            fma2p(acc[0][0], w.x, hd0); fma2p(acc[1][0], w.y, hd0);
            fma2p(acc[0][1], w.x, hd1); fma2p(acc[1][1], w.y, hd1);
        }
    }
}

// PhasedLSTM gate + time gate (fast mod via reciprocal + clamps; q < 1000 << 2^24)
__device__ __forceinline__ void plstm_gate2(float zi, float zf, float zg, float zo,
                                            float tcur, float tau, float itau, float s,
                                            float& h, float& c) {
    float ch = fsig(zf) * c + fsig(zi) * ftanh(zg);
    float hh = fsig(zo) * ftanh(ch);
    float d = tcur - s;
    float q = truncf(d * itau);
    float m = fmaf(-q, tau, d);
    m = (m < 0.0f)  ? m + tau : m;
    m = (m >= tau)  ? m - tau : m;
    m = (m < 0.0f)  ? m + tau : m;
    float phi = m * itau;
    float kg;
    if (phi < 0.5f * R_ON_)      kg = (2.0f * phi) / R_ON_;
    else if (phi < R_ON_)        kg = 2.0f - (2.0f * phi) / R_ON_;
    else                         kg = ALPHA_ * phi;
    h = kg * hh + (1.0f - kg) * h;
    c = kg * ch + (1.0f - kg) * c;
}

__global__ void __launch_bounds__(NTHR, 1) __cluster_dims__(CSZ, 1, 1)
plstm_cluster_kernel(const float* __restrict__ inputs, const float* __restrict__ times,
                     const float* __restrict__ gWx0, const float* __restrict__ gWh0,
                     const float* __restrict__ gb0,  const float* __restrict__ gtau0,
                     const float* __restrict__ gs0,  const float* __restrict__ gWx1,
                     const float* __restrict__ gWh1, const float* __restrict__ gb1,
                     const float* __restrict__ gtau1,const float* __restrict__ gs1,
                     const float* __restrict__ ggamma,const float* __restrict__ gbeta,
                     const float* __restrict__ gWfc, const float* __restrict__ gbfc,
                     float* __restrict__ out) {
    extern __shared__ float smraw[];
    SM& sm = *reinterpret_cast<SM*>(smraw);
    const int tid = threadIdx.x;
    uint32_t rank;
    asm("mov.u32 %0, %%cluster_ctarank;" : "=r"(rank));
    const int bstart = (blockIdx.x >> 2) * GC;

    const bool isA = (tid < 256);
    const int mt    = tid & 255;
    const int ks    = mt >> 7;
    const int mlane = mt & 31;
    const int wq    = (mt >> 5) & 3;
    const int bp    = mlane >> 3;
    const int quad  = wq * 8 + (mlane & 7);
    const int kbase = ks << 6;
    const int lcq   = quad * 4;
    // gate mapping (A): warp gb = batch, lane gj = own unit
    const int gb = tid >> 5, gj = tid & 31;

    // ---- one-time SMEM setup ----
    for (int i = tid; i < 128 * 128; i += NTHR) {
        int k = i >> 7, c = i & 127;
        int gcol = ((c >> 5) << 7) + ((int)rank << 5) + (c & 31);
        sm.Wh0s[i] = gWh0[k * 512 + gcol];
        sm.Wx1g[i] = gWx1[k * 512 + gcol];   // raw; scaled by gamma below
        sm.Wh1s[i] = gWh1[k * 512 + gcol];
    }
    for (int i = tid; i < NF * 128; i += NTHR) {
        int f = i >> 7, c = i & 127;
        int gcol = ((c >> 5) << 7) + ((int)rank << 5) + (c & 31);
        sm.Wx0s[i] = gWx0[f * 512 + gcol];
    }
    for (int c = tid; c < 128; c += NTHR) {
        int gcol = ((c >> 5) << 7) + ((int)rank << 5) + (c & 31);
        sm.b0s[c] = gb0[gcol];
        sm.b1s[c] = gb1[gcol];
    }
    if (tid < OWN) {
        int u = (int)rank * OWN + tid;
        float t0 = gtau0[u], t1 = gtau1[u];
        sm.tau0s[tid] = t0; sm.s0s[tid] = gs0[u]; sm.itau0s[tid] = 1.0f / t0;
        sm.tau1s[tid] = t1; sm.s1s[tid] = gs1[u]; sm.itau1s[tid] = 1.0f / t1;
    }
    for (int i = tid; i < OWN * NC + 32; i += NTHR)
        sm.Wfcs[i] = (i < OWN * NC) ? gWfc[((int)rank * OWN + i / NC) * NC + (i % NC)] : 0.0f;
    if (tid < NC) sm.bfcs[tid] = gbfc[tid];
    for (int i = tid; i < GC * HR; i += NTHR) { sm.h0f[i] = 0.0f; sm.h1f[i] = 0.0f; }
    if (tid < GC) {
        sm.tmb[0][tid] = times[(size_t)(bstart + tid) * TT];
        sm.tmb[1][tid] = times[(size_t)(bstart + tid) * TT + 1];
    }
    if (tid < GC * NF) {
        int g = tid / NF, f = tid - g * NF;
        sm.xb[0][g][f] = inputs[((size_t)(bstart + g) * TT) * NF + f];
        sm.xb[1][g][f] = inputs[((size_t)(bstart + g) * TT + 1) * NF + f];
    }
    const uint32_t mb1a = (uint32_t)__cvta_generic_to_shared(&sm.mbars[0]);
    const uint32_t mb2a = (uint32_t)__cvta_generic_to_shared(&sm.mbars[1]);
    if (tid == 0) { mbar_init(mb1a, CSZ); mbar_init(mb2a, CSZ); }
    __syncthreads();

    if (isA) {
        // Wx1g *= gamma[k]; per-slab col sums S1 (Wx1*gm), S2 (Wx1*bt)
        const int lc = tid & 127;
        float s1 = 0.0f, s2 = 0.0f;
        for (int k = 0; k < 64; ++k) {
            int kk = kbase + k;
            int ni = kk * 128 + lc;
            float w = sm.Wx1g[ni];
            float wg = w * ggamma[kk];
            sm.Wx1g[ni] = wg;
            s1 += wg;
            s2 += w * gbeta[kk];
        }
        sm.S1cs[ks][lc] = s1;
        sm.S2cs[ks][lc] = s2;
    } else {
        // pre-loop z0(0) = x(0)@Wx0 + b0 (h0 = 0)
        float* zp = sm.z0 + ks * 1024 + (2 * bp) * 128 + lcq;
        if (ks == 0) {
            float4 b0v = *reinterpret_cast<const float4*>(&sm.b0s[lcq]);
            float4 w0v = *reinterpret_cast<const float4*>(&sm.Wx0s[lcq]);
            float4 w1v = *reinterpret_cast<const float4*>(&sm.Wx0s[128 + lcq]);
            float4 w2v = *reinterpret_cast<const float4*>(&sm.Wx0s[256 + lcq]);
            #pragma unroll
            for (int d = 0; d < 2; ++d) {
                const float* x = sm.xb[0][2 * bp + d];
                float xa = x[0], xb_ = x[1], xc = x[2];
                zp[d * 128 + 0] = b0v.x + xa * w0v.x + xb_ * w1v.x + xc * w2v.x;
                zp[d * 128 + 1] = b0v.y + xa * w0v.y + xb_ * w1v.y + xc * w2v.y;
                zp[d * 128 + 2] = b0v.z + xa * w0v.z + xb_ * w1v.z + xc * w2v.z;
                zp[d * 128 + 3] = b0v.w + xa * w0v.w + xb_ * w1v.w + xc * w2v.w;
            }
        } else {
            #pragma unroll
            for (int d = 0; d < 2; ++d) {
                zp[d * 128 + 0] = 0.0f; zp[d * 128 + 1] = 0.0f;
                zp[d * 128 + 2] = 0.0f; zp[d * 128 + 3] = 0.0f;
            }
        }
    }
    CLUSTER_SYNC();   // all CTAs initialized (incl. mbarriers) before any remote traffic

    float* const zp0 = sm.z0 + ks * 1024 + (2 * bp) * 128 + lcq;
    float* const zp1 = sm.z1 + ks * 1024 + (2 * bp) * 128 + lcq;
    // A-thread persistent own state (unit u = rank*32+gj, batch gb)
    float h0own = 0.0f, c0own = 0.0f, h1own = 0.0f, c1own = 0.0f;
    const int uown = (int)rank * OWN + gj;
    const int packsrc = (gj & 7) * 4;       // lane source base for packed exchange
    const uint32_t dstrank = (uint32_t)(gj >> 3);

    for (int t = 0; t < TT; ++t) {
        const int par = t & 1, parn = par ^ 1;
        float tcur = 0.0f;
        unsigned long long acc0[2][2];

        // ===== P1: A: gates0 + packed h0 exchange + LN partials | B: Wh1@h1(t-1) =====
        if (isA) {
            const float* zb = sm.z0 + gb * 128;
            float zi = zb[gj]      + zb[1024 + gj];
            float zf = zb[32 + gj] + zb[1024 + 32 + gj];
            float zg = zb[64 + gj] + zb[1024 + 64 + gj];
            float zo = zb[96 + gj] + zb[1024 + 96 + gj];
            tcur = sm.tmb[par][gb];
            plstm_gate2(zi, zf, zg, zo, tcur,
                        sm.tau0s[gj], sm.itau0s[gj], sm.s0s[gj], h0own, c0own);
            // packed exchange: lane group (gj>>3) ships 32 own units as v4 to rank gj>>3
            float v0 = __shfl_sync(0xffffffffu, h0own, packsrc + 0);
            float v1 = __shfl_sync(0xffffffffu, h0own, packsrc + 1);
            float v2 = __shfl_sync(0xffffffffu, h0own, packsrc + 2);
            float v3 = __shfl_sync(0xffffffffu, h0own, packsrc + 3);
            uint32_t la = (uint32_t)__cvta_generic_to_shared(
                &sm.h0f[gb * HR + (int)rank * OWN + packsrc]);
            stc_v4(la, dstrank, v0, v1, v2, v3);
            float s = h0own, q = h0own * h0own;
            #pragma unroll
            for (int o = 16; o; o >>= 1) {
                s += __shfl_xor_sync(0xffffffffu, s, o);
                q += __shfl_xor_sync(0xffffffffu, q, o);
            }
            if (gj < 4) {
                uint32_t lr = (uint32_t)__cvta_generic_to_shared(
                    &sm.red2[(int)rank * GC + gb]);
                stc_v2(lr, (uint32_t)gj, s, q);
            }
        } else {
            unsigned long long accW[2][2];
            float4 s2v = *reinterpret_cast<const float4*>(&sm.S2cs[ks][lcq]);
            float c0 = s2v.x, c1 = s2v.y, c2 = s2v.z, c3 = s2v.w;
            if (ks == 0) {
                float4 b1v = *reinterpret_cast<const float4*>(&sm.b1s[lcq]);
                c0 += b1v.x; c1 += b1v.y; c2 += b1v.z; c3 += b1v.w;
            }
            accW[0][0] = pack2(c0, c1); accW[1][0] = pack2(c2, c3);
            accW[0][1] = accW[0][0];    accW[1][1] = accW[1][0];
            mv2(sm.Wh1s, &sm.h1f[(2 * bp) * HR], kbase, quad, accW);
            *reinterpret_cast<unsigned long long*>(zp1)       = accW[0][0];
            *reinterpret_cast<unsigned long long*>(zp1 + 2)   = accW[1][0];
            *reinterpret_cast<unsigned long long*>(zp1 + 128) = accW[0][1];
            *reinterpret_cast<unsigned long long*>(zp1 + 130) = accW[1][1];
        }
        // ===== S1: h0(t), LN partials, z1 pre-fold visible =====
        __syncthreads();
        if (tid == 0) mbar_arrive_all(mb1a);
        MBAR_WAIT(mb1a, par);

        // ===== P2: A: Wx1g@h0 + LN fold -> z1 | B: softmax(t-1), prefetch, next z0 =====
        if (isA) {
            unsigned long long A[2][2];
            A[0][0] = 0ull; A[0][1] = 0ull; A[1][0] = 0ull; A[1][1] = 0ull;
            mv2(sm.Wx1g, &sm.h0f[(2 * bp) * HR], kbase, quad, A);
            float4 S1v = *reinterpret_cast<const float4*>(&sm.S1cs[ks][lcq]);
            unsigned long long S1a = pack2(S1v.x, S1v.y);
            unsigned long long S1b = pack2(S1v.z, S1v.w);
            #pragma unroll
            for (int d = 0; d < 2; ++d) {
                int b = 2 * bp + d;
                float s4 = sm.red2[b].x + sm.red2[8 + b].x + sm.red2[16 + b].x + sm.red2[24 + b].x;
                float q4 = sm.red2[b].y + sm.red2[8 + b].y + sm.red2[16 + b].y + sm.red2[24 + b].y;
                float mu  = s4 * (1.0f / 128.0f);
                float var = fmaxf(q4 * (1.0f / 128.0f) - mu * mu, 0.0f);
                float rs  = rsqrtf(var + LN_EPS_);
                float rm  = -rs * mu;
                unsigned long long rs2 = pack2(rs, rs);
                unsigned long long rm2 = pack2(rm, rm);
                unsigned long long zw0 = *reinterpret_cast<unsigned long long*>(zp1 + d * 128);
                unsigned long long zw1 = *reinterpret_cast<unsigned long long*>(zp1 + d * 128 + 2);
                fma2p(zw0, rs2, A[0][d]); fma2p(zw0, rm2, S1a);
                fma2p(zw1, rs2, A[1][d]); fma2p(zw1, rm2, S1b);
                *reinterpret_cast<unsigned long long*>(zp1 + d * 128)     = zw0;
                *reinterpret_cast<unsigned long long*>(zp1 + d * 128 + 2) = zw1;
            }
        } else {
            // softmax for step t-1 (warp 8)
            if (tid < 288 && t > 0) {
                int bL = tid & 1, c2 = (tid & 31) >> 1;
                bool valid = (c2 < NC);
                const float* lr = sm.lrecv[parn];
                float lg = -1e30f;
                if (valid)
                    lg = sm.bfcs[c2]
                       + lr[(0 + bL) * 16 + c2] + lr[(2 + bL) * 16 + c2]
                       + lr[(4 + bL) * 16 + c2] + lr[(6 + bL) * 16 + c2];
                float mx = lg;
                #pragma unroll
                for (int o = 2; o < 32; o <<= 1)
                    mx = fmaxf(mx, __shfl_xor_sync(0xffffffffu, mx, o));
                float e = valid ? __expf(lg - mx) : 0.0f;
                float ssum = e;
                #pragma unroll
                for (int o = 2; o < 32; o <<= 1)
                    ssum += __shfl_xor_sync(0xffffffffu, ssum, o);
                if (valid)
                    out[((size_t)(bstart + (int)rank * 2 + bL) * TT + (t - 1)) * NC + c2]
                        = e * __fdividef(1.0f, ssum);
            }
            // x/t prefetch for t+2 (warp 9)
            if (t + 2 < TT) {
                if (tid >= 288 && tid < 288 + GC)
                    sm.tmb[par][tid - 288] = times[(size_t)(bstart + (tid - 288)) * TT + t + 2];
                if (tid >= 296 && tid < 296 + GC * NF) {
                    int ii = tid - 296;
                    int g = ii / NF, f = ii - g * NF;
                    sm.xb[par][g][f] = inputs[((size_t)(bstart + g) * TT + t + 2) * NF + f];
                }
            }
            // next z0 = x(t+1)@Wx0 + Wh0@h0(t) + b0, stored now (A reads after S2)
            if (t + 1 < TT) {
                if (ks == 0) {
                    float4 b0v = *reinterpret_cast<const float4*>(&sm.b0s[lcq]);
                    float4 w0v = *reinterpret_cast<const float4*>(&sm.Wx0s[lcq]);
                    float4 w1v = *reinterpret_cast<const float4*>(&sm.Wx0s[128 + lcq]);
                    float4 w2v = *reinterpret_cast<const float4*>(&sm.Wx0s[256 + lcq]);
                    #pragma unroll
                    for (int d = 0; d < 2; ++d) {
                        const float* x = sm.xb[parn][2 * bp + d];
                        float xa = x[0], xb_ = x[1], xc = x[2];
                        float v0 = b0v.x + xa * w0v.x + xb_ * w1v.x + xc * w2v.x;
                        float v1 = b0v.y + xa * w0v.y + xb_ * w1v.y + xc * w2v.y;
                        float v2 = b0v.z + xa * w0v.z + xb_ * w1v.z + xc * w2v.z;
                        float v3 = b0v.w + xa * w0v.w + xb_ * w1v.w + xc * w2v.w;
                        acc0[0][d] = pack2(v0, v1);
                        acc0[1][d] = pack2(v2, v3);
                    }
                } else {
                    acc0[0][0] = 0ull; acc0[0][1] = 0ull;
                    acc0[1][0] = 0ull; acc0[1][1] = 0ull;
                }
                mv2(sm.Wh0s, &sm.h0f[(2 * bp) * HR], kbase, quad, acc0);
                *reinterpret_cast<unsigned long long*>(zp0)       = acc0[0][0];
                *reinterpret_cast<unsigned long long*>(zp0 + 2)   = acc0[1][0];
                *reinterpret_cast<unsigned long long*>(zp0 + 128) = acc0[0][1];
                *reinterpret_cast<unsigned long long*>(zp0 + 130) = acc0[1][1];
            }
        }
        __syncthreads();                       // B3: z1 ready

        // ===== P3: A: gates1 + packed h1 exchange + FC partials | B: to S2 =====
        if (isA) {
            const float* zb = sm.z1 + gb * 128;
            float zi = zb[gj]      + zb[1024 + gj];
            float zf = zb[32 + gj] + zb[1024 + 32 + gj];
            float zg = zb[64 + gj] + zb[1024 + 64 + gj];
            float zo = zb[96 + gj] + zb[1024 + 96 + gj];
            plstm_gate2(zi, zf, zg, zo, tcur,
                        sm.tau1s[gj], sm.itau1s[gj], sm.s1s[gj], h1own, c1own);
            float v0 = __shfl_sync(0xffffffffu, h1own, packsrc + 0);
            float v1 = __shfl_sync(0xffffffffu, h1own, packsrc + 1);
            float v2 = __shfl_sync(0xffffffffu, h1own, packsrc + 2);
            float v3 = __shfl_sync(0xffffffffu, h1own, packsrc + 3);
            uint32_t la = (uint32_t)__cvta_generic_to_shared(
                &sm.h1f[gb * HR + (int)rank * OWN + packsrc]);
            stc_v4(la, dstrank, v0, v1, v2, v3);
            // FC partial over this warp's 32 own units; lane = class
            float a = 0.0f;
            #pragma unroll
            for (int j = 0; j < OWN; ++j)
                a = fmaf(__shfl_sync(0xffffffffu, h1own, j), sm.Wfcs[j * NC + gj], a);
            if (gj < NC) {
                int owner = gb >> 1, bL = gb & 1;
                uint32_t ad = (uint32_t)__cvta_generic_to_shared(
                    &sm.lrecv[par][((int)rank * 2 + bL) * 16 + gj]);
                stc_f32(ad, (uint32_t)owner, a);
            }
        }
        // ===== S2: h1(t), lrecv(t) visible; z1/h0f free for next step =====
        __syncthreads();
        if (tid == 0) mbar_arrive_all(mb2a);
        MBAR_WAIT(mb2a, par);
    }

    // ===== epilogue: softmax for the final step (TT-1) =====
    if (tid >= 256 && tid < 288) {
        const int pe = (TT - 1) & 1;
        int bL = tid & 1, c2 = (tid & 31) >> 1;
        bool valid = (c2 < NC);
        const float* lr = sm.lrecv[pe];
        float lg = -1e30f;
        if (valid)
            lg = sm.bfcs[c2]
               + lr[(0 + bL) * 16 + c2] + lr[(2 + bL) * 16 + c2]
               + lr[(4 + bL) * 16 + c2] + lr[(6 + bL) * 16 + c2];
        float mx = lg;
        #pragma unroll
        for (int o = 2; o < 32; o <<= 1)
            mx = fmaxf(mx, __shfl_xor_sync(0xffffffffu, mx, o));
        float e = valid ? __expf(lg - mx) : 0.0f;
        float ssum = e;
        #pragma unroll
        for (int o = 2; o < 32; o <<= 1)
            ssum += __shfl_xor_sync(0xffffffffu, ssum, o);
        if (valid)
            out[((size_t)(bstart + (int)rank * 2 + bL) * TT + (TT - 1)) * NC + c2]
                = e * __fdividef(1.0f, ssum);
    }
}

extern "C" void kernel_launch(void* const* d_in, const int* in_sizes, int n_in,
                              void* d_out, int out_size) {
    const float* inputs = (const float*)d_in[0];
    const float* times  = (const float*)d_in[1];
    const float* Wx0    = (const float*)d_in[2];
    const float* Wh0    = (const float*)d_in[3];
    const float* b0     = (const float*)d_in[4];
    const float* tau0   = (const float*)d_in[5];
    const float* s0     = (const float*)d_in[6];
    const float* Wx1    = (const float*)d_in[7];
    const float* Wh1    = (const float*)d_in[8];
    const float* b1     = (const float*)d_in[9];
    const float* tau1   = (const float*)d_in[10];
    const float* s1     = (const float*)d_in[11];
    const float* gamma  = (const float*)d_in[12];
    const float* beta   = (const float*)d_in[13];
    const float* Wfc    = (const float*)d_in[14];
    const float* bfc    = (const float*)d_in[15];

    cudaFuncSetAttribute(plstm_cluster_kernel,
                         cudaFuncAttributeMaxDynamicSharedMemorySize,
                         (int)sizeof(SM));
    plstm_cluster_kernel<<<NCTA, NTHR, sizeof(SM)>>>(
        inputs, times, Wx0, Wh0, b0, tau0, s0,
        Wx1, Wh1, b1, tau1, s1, gamma, beta, Wfc, bfc, (float*)d_out);
}

// round 15
// speedup vs baseline: 1.2321x; 1.2321x over previous
#include <cuda_runtime.h>
#include <math.h>
#include <stdint.h>

// Problem constants
#define U      128
#define NC     10
#define NF     3
#define TT     1000
#define BB     256
#define CSZ    4              // CTAs per cluster
#define GC     8              // batch elements per cluster
#define OWN    32             // units owned per CTA
#define NTHR   512            // group A (0-255) recurrence path, group B (256-511) off-path
#define NCTA   128            // (BB/GC)*CSZ
#define HR     132            // h row stride in floats ([b][u] layout, bank-skewed, 16B-mult)

#define R_ON_   0.05f
#define ALPHA_  0.001f
#define LN_EPS_ 1e-3f

// ---- packed f32x2 helpers (FFMA2: 2x fp32 MAC throughput) ----
__device__ __forceinline__ unsigned long long pack2(float a, float b) {
    unsigned long long r;
    asm("mov.b64 %0, {%1, %2};" : "=l"(r) : "f"(a), "f"(b));
    return r;
}
__device__ __forceinline__ void fma2p(unsigned long long& acc,
                                      unsigned long long a,
                                      unsigned long long b) {
    asm("fma.rn.f32x2 %0, %1, %2, %0;" : "+l"(acc) : "l"(a), "l"(b));
}

// ---- fast transcendental helpers (rel err ~1e-6, budget is 1e-3) ----
__device__ __forceinline__ float fsig(float x) {
    return __fdividef(1.0f, 1.0f + __expf(-x));
}
__device__ __forceinline__ float ftanh(float x) {
    float ax = fabsf(x);
    float e  = __expf(-2.0f * ax);
    float t  = __fdividef(1.0f - e, 1.0f + e);
    return copysignf(t, x);
}

// hardware cluster barrier (all threads of all 4 CTAs; subsumes __syncthreads)
#define CLUSTER_SYNC() do { \
    asm volatile("barrier.cluster.arrive.aligned;" ::: "memory"); \
    asm volatile("barrier.cluster.wait.aligned;"   ::: "memory"); } while (0)

// ---- DSMEM stores (packed) ----
__device__ __forceinline__ void stc_f32(uint32_t la, uint32_t r, float v) {
    uint32_t ra;
    asm volatile("mapa.shared::cluster.u32 %0, %1, %2;" : "=r"(ra) : "r"(la), "r"(r));
    asm volatile("st.shared::cluster.f32 [%0], %1;" :: "r"(ra), "f"(v) : "memory");
}
__device__ __forceinline__ void stc_v2(uint32_t la, uint32_t r, float a, float b) {
    uint32_t ra;
    asm volatile("mapa.shared::cluster.u32 %0, %1, %2;" : "=r"(ra) : "r"(la), "r"(r));
    asm volatile("st.shared::cluster.v2.f32 [%0], {%1, %2};"
                 :: "r"(ra), "f"(a), "f"(b) : "memory");
}
__device__ __forceinline__ void stc_v4(uint32_t la, uint32_t r,
                                       float a, float b, float c, float d) {
    uint32_t ra;
    asm volatile("mapa.shared::cluster.u32 %0, %1, %2;" : "=r"(ra) : "r"(la), "r"(r));
    asm volatile("st.shared::cluster.v4.f32 [%0], {%1, %2, %3, %4};"
                 :: "r"(ra), "f"(a), "f"(b), "f"(c), "f"(d) : "memory");
}

// Dynamic SMEM: ~229.9 KB (<= 232448 B limit, 1 CTA/SM)
struct __align__(16) SM {
    float Wh0s[128 * 128];      // own 128 cols (gate-interleaved) of Wh0, plain [k][lc]
    float Wx1g[128 * 128];      // own cols of Wx1 * gamma[k]
    float Wh1s[128 * 128];
    float z0[2 * 8 * 128];      // layer-0 pre-activations [ks][b][lc]
    float z1[2 * 8 * 128];      // layer-1 pre-activations (pre-fold + fold)
    float h0f[GC * HR];         // h0, [b*HR + unit], single-buffered
    float h1f[GC * HR];         // h1, same layout
    float Wx0s[NF * 128];       // own cols of Wx0 [f][lc]
    float b0s[128], b1s[128];   // own cols of biases
    float S1cs[2][128];         // per-slab col sums of Wx1g
    float S2cs[2][128];         // per-slab col sums of Wx1*beta
    float tau0s[OWN], s0s[OWN], itau0s[OWN];
    float tau1s[OWN], s1s[OWN], itau1s[OWN];
    float Wfcs[OWN * NC + 32];  // own rows of Wfc (padded)
    float bfcs[16];
    float2 red2[CSZ * GC];      // LN partials {sum, sumsq} [srcRank*8 + b]
    float lrecv[2][CSZ * 2 * 16];  // logit partials, double-buffered by parity
    float xb[2][GC][4];         // double-buffered inputs (f padded to 4)
    float tmb[2][GC];           // double-buffered times
};

// One 64-row K-slab: 4 cols (quad) x 2 batches (bpair) per thread.
__device__ __forceinline__ void mv2(const float* __restrict__ Ws,
                                    const float* __restrict__ hb0,
                                    int kbase, int quad,
                                    unsigned long long acc[2][2]) {
    const ulonglong2* w2 = reinterpret_cast<const ulonglong2*>(Ws + kbase * 128) + quad;
    const float* h0p = hb0 + kbase;          // batch 2bp
    const float* h1p = hb0 + HR + kbase;     // batch 2bp+1
    #pragma unroll 8
    for (int k4 = 0; k4 < 16; ++k4) {
        float4 ha = *reinterpret_cast<const float4*>(h0p + 4 * k4);
        float4 hb = *reinterpret_cast<const float4*>(h1p + 4 * k4);
        float hav[4] = {ha.x, ha.y, ha.z, ha.w};
        float hbv[4] = {hb.x, hb.y, hb.z, hb.w};
        #pragma unroll
        for (int j = 0; j < 4; ++j) {
            ulonglong2 w = w2[(4 * k4 + j) * 32];
            unsigned long long hd0 = pack2(hav[j], hav[j]);
            unsigned long long hd1 = pack2(hbv[j], hbv[j]);
            fma2p(acc[0][0], w.x, hd0); fma2p(acc[1][0], w.y, hd0);
            fma2p(acc[0][1], w.x, hd1); fma2p(acc[1][1], w.y, hd1);
        }
    }
}

// PhasedLSTM gate + time gate (fast mod via reciprocal + clamps; q < 1000 << 2^24)
__device__ __forceinline__ void plstm_gate2(float zi, float zf, float zg, float zo,
                                            float tcur, float tau, float itau, float s,
                                            float& h, float& c) {
    float ch = fsig(zf) * c + fsig(zi) * ftanh(zg);
    float hh = fsig(zo) * ftanh(ch);
    float d = tcur - s;
    float q = truncf(d * itau);
    float m = fmaf(-q, tau, d);
    m = (m < 0.0f)  ? m + tau : m;
    m = (m >= tau)  ? m - tau : m;
    m = (m < 0.0f)  ? m + tau : m;
    float phi = m * itau;
    float kg;
    if (phi < 0.5f * R_ON_)      kg = (2.0f * phi) / R_ON_;
    else if (phi < R_ON_)        kg = 2.0f - (2.0f * phi) / R_ON_;
    else                         kg = ALPHA_ * phi;
    h = kg * hh + (1.0f - kg) * h;
    c = kg * ch + (1.0f - kg) * c;
}

__global__ void __launch_bounds__(NTHR, 1) __cluster_dims__(CSZ, 1, 1)
plstm_cluster_kernel(const float* __restrict__ inputs, const float* __restrict__ times,
                     const float* __restrict__ gWx0, const float* __restrict__ gWh0,
                     const float* __restrict__ gb0,  const float* __restrict__ gtau0,
                     const float* __restrict__ gs0,  const float* __restrict__ gWx1,
                     const float* __restrict__ gWh1, const float* __restrict__ gb1,
                     const float* __restrict__ gtau1,const float* __restrict__ gs1,
                     const float* __restrict__ ggamma,const float* __restrict__ gbeta,
                     const float* __restrict__ gWfc, const float* __restrict__ gbfc,
                     float* __restrict__ out) {
    extern __shared__ float smraw[];
    SM& sm = *reinterpret_cast<SM*>(smraw);
    const int tid = threadIdx.x;
    uint32_t rank;
    asm("mov.u32 %0, %%cluster_ctarank;" : "=r"(rank));
    const int bstart = (blockIdx.x >> 2) * GC;

    const bool isA = (tid < 256);
    const int mt    = tid & 255;
    const int ks    = mt >> 7;
    const int mlane = mt & 31;
    const int wq    = (mt >> 5) & 3;
    const int bp    = mlane >> 3;
    const int quad  = wq * 8 + (mlane & 7);
    const int kbase = ks << 6;
    const int lcq   = quad * 4;
    // gate mapping (A): warp gb = batch, lane gj = own unit
    const int gb = tid >> 5, gj = tid & 31;

    // ---- one-time SMEM setup ----
    for (int i = tid; i < 128 * 128; i += NTHR) {
        int k = i >> 7, c = i & 127;
        int gcol = ((c >> 5) << 7) + ((int)rank << 5) + (c & 31);
        sm.Wh0s[i] = gWh0[k * 512 + gcol];
        sm.Wx1g[i] = gWx1[k * 512 + gcol];   // raw; scaled by gamma below
        sm.Wh1s[i] = gWh1[k * 512 + gcol];
    }
    for (int i = tid; i < NF * 128; i += NTHR) {
        int f = i >> 7, c = i & 127;
        int gcol = ((c >> 5) << 7) + ((int)rank << 5) + (c & 31);
        sm.Wx0s[i] = gWx0[f * 512 + gcol];
    }
    for (int c = tid; c < 128; c += NTHR) {
        int gcol = ((c >> 5) << 7) + ((int)rank << 5) + (c & 31);
        sm.b0s[c] = gb0[gcol];
        sm.b1s[c] = gb1[gcol];
    }
    if (tid < OWN) {
        int u = (int)rank * OWN + tid;
        float t0 = gtau0[u], t1 = gtau1[u];
        sm.tau0s[tid] = t0; sm.s0s[tid] = gs0[u]; sm.itau0s[tid] = 1.0f / t0;
        sm.tau1s[tid] = t1; sm.s1s[tid] = gs1[u]; sm.itau1s[tid] = 1.0f / t1;
    }
    for (int i = tid; i < OWN * NC + 32; i += NTHR)
        sm.Wfcs[i] = (i < OWN * NC) ? gWfc[((int)rank * OWN + i / NC) * NC + (i % NC)] : 0.0f;
    if (tid < NC) sm.bfcs[tid] = gbfc[tid];
    for (int i = tid; i < GC * HR; i += NTHR) { sm.h0f[i] = 0.0f; sm.h1f[i] = 0.0f; }
    if (tid < GC) {
        sm.tmb[0][tid] = times[(size_t)(bstart + tid) * TT];
        sm.tmb[1][tid] = times[(size_t)(bstart + tid) * TT + 1];
    }
    if (tid < GC * NF) {
        int g = tid / NF, f = tid - g * NF;
        sm.xb[0][g][f] = inputs[((size_t)(bstart + g) * TT) * NF + f];
        sm.xb[1][g][f] = inputs[((size_t)(bstart + g) * TT + 1) * NF + f];
    }
    __syncthreads();

    if (isA) {
        // Wx1g *= gamma[k]; per-slab col sums S1 (Wx1*gm), S2 (Wx1*bt)
        const int lc = tid & 127;
        float s1 = 0.0f, s2 = 0.0f;
        for (int k = 0; k < 64; ++k) {
            int kk = kbase + k;
            int ni = kk * 128 + lc;
            float w = sm.Wx1g[ni];
            float wg = w * ggamma[kk];
            sm.Wx1g[ni] = wg;
            s1 += wg;
            s2 += w * gbeta[kk];
        }
        sm.S1cs[ks][lc] = s1;
        sm.S2cs[ks][lc] = s2;
    } else {
        // pre-loop z0(0) = x(0)@Wx0 + b0 (h0 = 0)
        float* zp = sm.z0 + ks * 1024 + (2 * bp) * 128 + lcq;
        if (ks == 0) {
            float4 b0v = *reinterpret_cast<const float4*>(&sm.b0s[lcq]);
            float4 w0v = *reinterpret_cast<const float4*>(&sm.Wx0s[lcq]);
            float4 w1v = *reinterpret_cast<const float4*>(&sm.Wx0s[128 + lcq]);
            float4 w2v = *reinterpret_cast<const float4*>(&sm.Wx0s[256 + lcq]);
            #pragma unroll
            for (int d = 0; d < 2; ++d) {
                const float* x = sm.xb[0][2 * bp + d];
                float xa = x[0], xb_ = x[1], xc = x[2];
                zp[d * 128 + 0] = b0v.x + xa * w0v.x + xb_ * w1v.x + xc * w2v.x;
                zp[d * 128 + 1] = b0v.y + xa * w0v.y + xb_ * w1v.y + xc * w2v.y;
                zp[d * 128 + 2] = b0v.z + xa * w0v.z + xb_ * w1v.z + xc * w2v.z;
                zp[d * 128 + 3] = b0v.w + xa * w0v.w + xb_ * w1v.w + xc * w2v.w;
            }
        } else {
            #pragma unroll
            for (int d = 0; d < 2; ++d) {
                zp[d * 128 + 0] = 0.0f; zp[d * 128 + 1] = 0.0f;
                zp[d * 128 + 2] = 0.0f; zp[d * 128 + 3] = 0.0f;
            }
        }
    }
    CLUSTER_SYNC();   // all CTAs initialized before any remote traffic

    float* const zp0 = sm.z0 + ks * 1024 + (2 * bp) * 128 + lcq;
    float* const zp1 = sm.z1 + ks * 1024 + (2 * bp) * 128 + lcq;
    // A-thread persistent own state (unit u = rank*32+gj, batch gb)
    float h0own = 0.0f, c0own = 0.0f, h1own = 0.0f, c1own = 0.0f;
    const int packsrc = (gj & 7) * 4;       // lane source base for packed exchange
    const uint32_t dstrank = (uint32_t)(gj >> 3);

    for (int t = 0; t < TT; ++t) {
        const int par = t & 1, parn = par ^ 1;
        float tcur = 0.0f;
        unsigned long long acc0[2][2];

        // ===== P1: A: gates0 + packed h0 exchange + LN partials | B: Wh1@h1(t-1) =====
        if (isA) {
            const float* zb = sm.z0 + gb * 128;
            float zi = zb[gj]      + zb[1024 + gj];
            float zf = zb[32 + gj] + zb[1024 + 32 + gj];
            float zg = zb[64 + gj] + zb[1024 + 64 + gj];
            float zo = zb[96 + gj] + zb[1024 + 96 + gj];
            tcur = sm.tmb[par][gb];
            plstm_gate2(zi, zf, zg, zo, tcur,
                        sm.tau0s[gj], sm.itau0s[gj], sm.s0s[gj], h0own, c0own);
            // packed exchange: lane group (gj>>3) ships 32 own units as v4 to rank gj>>3
            float v0 = __shfl_sync(0xffffffffu, h0own, packsrc + 0);
            float v1 = __shfl_sync(0xffffffffu, h0own, packsrc + 1);
            float v2 = __shfl_sync(0xffffffffu, h0own, packsrc + 2);
            float v3 = __shfl_sync(0xffffffffu, h0own, packsrc + 3);
            uint32_t la = (uint32_t)__cvta_generic_to_shared(
                &sm.h0f[gb * HR + (int)rank * OWN + packsrc]);
            stc_v4(la, dstrank, v0, v1, v2, v3);
            float s = h0own, q = h0own * h0own;
            #pragma unroll
            for (int o = 16; o; o >>= 1) {
                s += __shfl_xor_sync(0xffffffffu, s, o);
                q += __shfl_xor_sync(0xffffffffu, q, o);
            }
            if (gj < 4) {
                uint32_t lr = (uint32_t)__cvta_generic_to_shared(
                    &sm.red2[(int)rank * GC + gb]);
                stc_v2(lr, (uint32_t)gj, s, q);
            }
        } else {
            unsigned long long accW[2][2];
            float4 s2v = *reinterpret_cast<const float4*>(&sm.S2cs[ks][lcq]);
            float c0 = s2v.x, c1 = s2v.y, c2 = s2v.z, c3 = s2v.w;
            if (ks == 0) {
                float4 b1v = *reinterpret_cast<const float4*>(&sm.b1s[lcq]);
                c0 += b1v.x; c1 += b1v.y; c2 += b1v.z; c3 += b1v.w;
            }
            accW[0][0] = pack2(c0, c1); accW[1][0] = pack2(c2, c3);
            accW[0][1] = accW[0][0];    accW[1][1] = accW[1][0];
            mv2(sm.Wh1s, &sm.h1f[(2 * bp) * HR], kbase, quad, accW);
            *reinterpret_cast<unsigned long long*>(zp1)       = accW[0][0];
            *reinterpret_cast<unsigned long long*>(zp1 + 2)   = accW[1][0];
            *reinterpret_cast<unsigned long long*>(zp1 + 128) = accW[0][1];
            *reinterpret_cast<unsigned long long*>(zp1 + 130) = accW[1][1];
        }
        CLUSTER_SYNC();        // S1: h0(t), LN partials, z1 pre-fold visible

        // ===== P2: A: Wx1g@h0 + LN fold -> z1 | B: softmax(t-1), prefetch, next z0 =====
        if (isA) {
            unsigned long long A[2][2];
            A[0][0] = 0ull; A[0][1] = 0ull; A[1][0] = 0ull; A[1][1] = 0ull;
            mv2(sm.Wx1g, &sm.h0f[(2 * bp) * HR], kbase, quad, A);
            float4 S1v = *reinterpret_cast<const float4*>(&sm.S1cs[ks][lcq]);
            unsigned long long S1a = pack2(S1v.x, S1v.y);
            unsigned long long S1b = pack2(S1v.z, S1v.w);
            #pragma unroll
            for (int d = 0; d < 2; ++d) {
                int b = 2 * bp + d;
                float s4 = sm.red2[b].x + sm.red2[8 + b].x + sm.red2[16 + b].x + sm.red2[24 + b].x;
                float q4 = sm.red2[b].y + sm.red2[8 + b].y + sm.red2[16 + b].y + sm.red2[24 + b].y;
                float mu  = s4 * (1.0f / 128.0f);
                float var = fmaxf(q4 * (1.0f / 128.0f) - mu * mu, 0.0f);
                float rs  = rsqrtf(var + LN_EPS_);
                float rm  = -rs * mu;
                unsigned long long rs2 = pack2(rs, rs);
                unsigned long long rm2 = pack2(rm, rm);
                unsigned long long zw0 = *reinterpret_cast<unsigned long long*>(zp1 + d * 128);
                unsigned long long zw1 = *reinterpret_cast<unsigned long long*>(zp1 + d * 128 + 2);
                fma2p(zw0, rs2, A[0][d]); fma2p(zw0, rm2, S1a);
                fma2p(zw1, rs2, A[1][d]); fma2p(zw1, rm2, S1b);
                *reinterpret_cast<unsigned long long*>(zp1 + d * 128)     = zw0;
                *reinterpret_cast<unsigned long long*>(zp1 + d * 128 + 2) = zw1;
            }
        } else {
            // softmax for step t-1 (warp 8)
            if (tid < 288 && t > 0) {
                int bL = tid & 1, c2 = (tid & 31) >> 1;
                bool valid = (c2 < NC);
                const float* lr = sm.lrecv[parn];
                float lg = -1e30f;
                if (valid)
                    lg = sm.bfcs[c2]
                       + lr[(0 + bL) * 16 + c2] + lr[(2 + bL) * 16 + c2]
                       + lr[(4 + bL) * 16 + c2] + lr[(6 + bL) * 16 + c2];
                float mx = lg;
                #pragma unroll
                for (int o = 2; o < 32; o <<= 1)
                    mx = fmaxf(mx, __shfl_xor_sync(0xffffffffu, mx, o));
                float e = valid ? __expf(lg - mx) : 0.0f;
                float ssum = e;
                #pragma unroll
                for (int o = 2; o < 32; o <<= 1)
                    ssum += __shfl_xor_sync(0xffffffffu, ssum, o);
                if (valid)
                    out[((size_t)(bstart + (int)rank * 2 + bL) * TT + (t - 1)) * NC + c2]
                        = e * __fdividef(1.0f, ssum);
            }
            // x/t prefetch for t+2 (warp 9)
            if (t + 2 < TT) {
                if (tid >= 288 && tid < 288 + GC)
                    sm.tmb[par][tid - 288] = times[(size_t)(bstart + (tid - 288)) * TT + t + 2];
                if (tid >= 296 && tid < 296 + GC * NF) {
                    int ii = tid - 296;
                    int g = ii / NF, f = ii - g * NF;
                    sm.xb[par][g][f] = inputs[((size_t)(bstart + g) * TT + t + 2) * NF + f];
                }
            }
            // next z0 = x(t+1)@Wx0 + Wh0@h0(t) + b0 (A reads it next iter, after S2)
            if (t + 1 < TT) {
                if (ks == 0) {
                    float4 b0v = *reinterpret_cast<const float4*>(&sm.b0s[lcq]);
                    float4 w0v = *reinterpret_cast<const float4*>(&sm.Wx0s[lcq]);
                    float4 w1v = *reinterpret_cast<const float4*>(&sm.Wx0s[128 + lcq]);
                    float4 w2v = *reinterpret_cast<const float4*>(&sm.Wx0s[256 + lcq]);
                    #pragma unroll
                    for (int d = 0; d < 2; ++d) {
                        const float* x = sm.xb[parn][2 * bp + d];
                        float xa = x[0], xb_ = x[1], xc = x[2];
                        float v0 = b0v.x + xa * w0v.x + xb_ * w1v.x + xc * w2v.x;
                        float v1 = b0v.y + xa * w0v.y + xb_ * w1v.y + xc * w2v.y;
                        float v2 = b0v.z + xa * w0v.z + xb_ * w1v.z + xc * w2v.z;
                        float v3 = b0v.w + xa * w0v.w + xb_ * w1v.w + xc * w2v.w;
                        acc0[0][d] = pack2(v0, v1);
                        acc0[1][d] = pack2(v2, v3);
                    }
                } else {
                    acc0[0][0] = 0ull; acc0[0][1] = 0ull;
                    acc0[1][0] = 0ull; acc0[1][1] = 0ull;
                }
                mv2(sm.Wh0s, &sm.h0f[(2 * bp) * HR], kbase, quad, acc0);
                *reinterpret_cast<unsigned long long*>(zp0)       = acc0[0][0];
                *reinterpret_cast<unsigned long long*>(zp0 + 2)   = acc0[1][0];
                *reinterpret_cast<unsigned long long*>(zp0 + 128) = acc0[0][1];
                *reinterpret_cast<unsigned long long*>(zp0 + 130) = acc0[1][1];
            }
        }
        __syncthreads();                       // B3: z1 ready

        // ===== P3: A: gates1 + packed h1 exchange + FC partials | B: to S2 =====
        if (isA) {
            const float* zb = sm.z1 + gb * 128;
            float zi = zb[gj]      + zb[1024 + gj];
            float zf = zb[32 + gj] + zb[1024 + 32 + gj];
            float zg = zb[64 + gj] + zb[1024 + 64 + gj];
            float zo = zb[96 + gj] + zb[1024 + 96 + gj];
            plstm_gate2(zi, zf, zg, zo, tcur,
                        sm.tau1s[gj], sm.itau1s[gj], sm.s1s[gj], h1own, c1own);
            float v0 = __shfl_sync(0xffffffffu, h1own, packsrc + 0);
            float v1 = __shfl_sync(0xffffffffu, h1own, packsrc + 1);
            float v2 = __shfl_sync(0xffffffffu, h1own, packsrc + 2);
            float v3 = __shfl_sync(0xffffffffu, h1own, packsrc + 3);
            uint32_t la = (uint32_t)__cvta_generic_to_shared(
                &sm.h1f[gb * HR + (int)rank * OWN + packsrc]);
            stc_v4(la, dstrank, v0, v1, v2, v3);
            // FC partial over this warp's 32 own units; lane = class
            float a = 0.0f;
            #pragma unroll
            for (int j = 0; j < OWN; ++j)
                a = fmaf(__shfl_sync(0xffffffffu, h1own, j), sm.Wfcs[j * NC + gj], a);
            if (gj < NC) {
                int owner = gb >> 1, bL = gb & 1;
                uint32_t ad = (uint32_t)__cvta_generic_to_shared(
                    &sm.lrecv[par][((int)rank * 2 + bL) * 16 + gj]);
                stc_f32(ad, (uint32_t)owner, a);
            }
        }
        CLUSTER_SYNC();        // S2: h1(t), lrecv(t) visible; z1/h0f free for next step
    }

    // ===== epilogue: softmax for the final step (TT-1) =====
    if (tid >= 256 && tid < 288) {
        const int pe = (TT - 1) & 1;
        int bL = tid & 1, c2 = (tid & 31) >> 1;
        bool valid = (c2 < NC);
        const float* lr = sm.lrecv[pe];
        float lg = -1e30f;
        if (valid)
            lg = sm.bfcs[c2]
               + lr[(0 + bL) * 16 + c2] + lr[(2 + bL) * 16 + c2]
               + lr[(4 + bL) * 16 + c2] + lr[(6 + bL) * 16 + c2];
        float mx = lg;
        #pragma unroll
        for (int o = 2; o < 32; o <<= 1)
            mx = fmaxf(mx, __shfl_xor_sync(0xffffffffu, mx, o));
        float e = valid ? __expf(lg - mx) : 0.0f;
        float ssum = e;
        #pragma unroll
        for (int o = 2; o < 32; o <<= 1)
            ssum += __shfl_xor_sync(0xffffffffu, ssum, o);
        if (valid)
            out[((size_t)(bstart + (int)rank * 2 + bL) * TT + (TT - 1)) * NC + c2]
                = e * __fdividef(1.0f, ssum);
    }
}

extern "C" void kernel_launch(void* const* d_in, const int* in_sizes, int n_in,
                              void* d_out, int out_size) {
    const float* inputs = (const float*)d_in[0];
    const float* times  = (const float*)d_in[1];
    const float* Wx0    = (const float*)d_in[2];
    const float* Wh0    = (const float*)d_in[3];
    const float* b0     = (const float*)d_in[4];
    const float* tau0   = (const float*)d_in[5];
    const float* s0     = (const float*)d_in[6];
    const float* Wx1    = (const float*)d_in[7];
    const float* Wh1    = (const float*)d_in[8];
    const float* b1     = (const float*)d_in[9];
    const float* tau1   = (const float*)d_in[10];
    const float* s1     = (const float*)d_in[11];
    const float* gamma  = (const float*)d_in[12];
    const float* beta   = (const float*)d_in[13];
    const float* Wfc    = (const float*)d_in[14];
    const float* bfc    = (const float*)d_in[15];

    cudaFuncSetAttribute(plstm_cluster_kernel,
                         cudaFuncAttributeMaxDynamicSharedMemorySize,
                         (int)sizeof(SM));
    plstm_cluster_kernel<<<NCTA, NTHR, sizeof(SM)>>>(
        inputs, times, Wx0, Wh0, b0, tau0, s0,
        Wx1, Wh1, b1, tau1, s1, gamma, beta, Wfc, bfc, (float*)d_out);
}